// round 4
// baseline (speedup 1.0000x reference)
#include <cuda_runtime.h>
#include <cuda_bf16.h>
#include <cstdint>

// Problem dims
#define BATCH 32
#define TLEN  2048
#define IDIM  512
#define HEADS 16
#define DDIM  64
#define MROWS (BATCH * TLEN)      // 65536
#define NCOLS (HEADS * DDIM)      // 1024 per c-slice
#define KTOT  1536                // 3 * IDIM (bf16 hi/lo split GEMM)

// GEMM tiling
#define BM 128
#define BN 128
#define BK 32
#define NT (KTOT / BK)            // 48
#define STAGES 4
#define ROWB 80                   // 32*2 + 16 pad (conflict-free ldmatrix)
#define STAGE_BYTES (128 * ROWB)  // 10240
#define SMEM_V  (2 * STAGES * STAGE_BYTES)   // 81920 (A + B)
#define SMEM_KQ (3 * STAGES * STAGE_BYTES)   // 122880 (A + Bk + Bq)

// Scratch (device globals; allocation-free)
__device__ __nv_bfloat16 g_xs[(size_t)MROWS * KTOT];            // 192 MB split-X [m][k]
__device__ __nv_bfloat16 g_ws[3ull * NCOLS * KTOT];             // 9 MB split-W [c][n][k]
__device__ float g_v[(size_t)MROWS * NCOLS];                    // 256 MB v proj [m][n]
__device__ float g_s[(size_t)BATCH * HEADS * TLEN];             // 4 MB scores [bh][t]

// ---------------------------------------------------------------------------
// PTX helpers (family-portable)
// ---------------------------------------------------------------------------
__device__ __forceinline__ uint32_t smem_u32(const void* p) {
    uint32_t a;
    asm("{ .reg .u64 t; cvta.to.shared.u64 t, %1; cvt.u32.u64 %0, t; }" : "=r"(a) : "l"(p));
    return a;
}
__device__ __forceinline__ void cp_async16(uint32_t dst, const void* src) {
    asm volatile("cp.async.cg.shared.global [%0], [%1], 16;" :: "r"(dst), "l"(src));
}
__device__ __forceinline__ void cp_commit() { asm volatile("cp.async.commit_group;" ::: "memory"); }
__device__ __forceinline__ void cp_wait2()  { asm volatile("cp.async.wait_group 2;" ::: "memory"); }

__device__ __forceinline__ void ldsm_x4(uint32_t* r, uint32_t addr) {
    asm volatile("ldmatrix.sync.aligned.m8n8.x4.shared.b16 {%0,%1,%2,%3}, [%4];"
                 : "=r"(r[0]), "=r"(r[1]), "=r"(r[2]), "=r"(r[3]) : "r"(addr));
}
__device__ __forceinline__ void mma16816(float* c, const uint32_t* a, uint32_t b0, uint32_t b1) {
    asm volatile("mma.sync.aligned.m16n8k16.row.col.f32.bf16.bf16.f32 "
                 "{%0,%1,%2,%3}, {%4,%5,%6,%7}, {%8,%9}, {%0,%1,%2,%3};"
                 : "+f"(c[0]), "+f"(c[1]), "+f"(c[2]), "+f"(c[3])
                 : "r"(a[0]), "r"(a[1]), "r"(a[2]), "r"(a[3]), "r"(b0), "r"(b1));
}

// ---------------------------------------------------------------------------
// K0a: split X -> bf16 blocks: Xs[m][0:512)=hi, [512:1024)=lo, [1024:1536)=hi
// ---------------------------------------------------------------------------
__global__ void convx_kernel(const float* __restrict__ x) {
    size_t e = (size_t)blockIdx.x * blockDim.x + threadIdx.x;
    if (e >= (size_t)MROWS * IDIM) return;
    size_t m = e >> 9;
    int k = (int)(e & 511);
    float v = x[e];
    __nv_bfloat16 hi = __float2bfloat16(v);
    __nv_bfloat16 lo = __float2bfloat16(v - __bfloat162float(hi));
    __nv_bfloat16* row = g_xs + m * KTOT;
    row[k] = hi;
    row[512 + k] = lo;
    row[1024 + k] = hi;
}

// ---------------------------------------------------------------------------
// K0b: split W -> Ws[c][n][0:512)=hi, [512:1024)=hi, [1024:1536)=lo
// ---------------------------------------------------------------------------
__global__ void convw_kernel(const float* __restrict__ W) {
    size_t e = (size_t)blockIdx.x * blockDim.x + threadIdx.x;
    if (e >= 3ull * IDIM * NCOLS) return;
    int c = (int)(e / (IDIM * NCOLS));
    int r = (int)(e % (IDIM * NCOLS));
    int k = r >> 10;
    int n = r & 1023;
    int h = n >> 6, d = n & 63;
    float v = W[(size_t)k * (HEADS * DDIM * 3) + h * (DDIM * 3) + d * 3 + c];
    __nv_bfloat16 hi = __float2bfloat16(v);
    __nv_bfloat16 lo = __float2bfloat16(v - __bfloat162float(hi));
    __nv_bfloat16* base = g_ws + ((size_t)c * NCOLS + n) * KTOT;
    base[k] = hi;
    base[512 + k] = hi;
    base[1024 + k] = lo;
}

// ---------------------------------------------------------------------------
// K1a: fused k+q GEMM -> scores only. Dual accumulators (k & q share the A
//      tile); epilogue does per-row q.k dot in registers, writes s (4 MB).
// ---------------------------------------------------------------------------
__global__ __launch_bounds__(256) void gemm_kq_kernel() {
    extern __shared__ char smem[];
    const int tid = threadIdx.x;
    const int wid = tid >> 5;
    const int lane = tid & 31;

    const int bn = blockIdx.x * BN;              // 0..896 (2 heads per CTA)
    const int bm = blockIdx.y * BM;
    const int wm = wid & 3;
    const int wn = wid >> 2;

    const uint32_t sb = smem_u32(smem);
    const uint32_t aBase = sb;
    const uint32_t kBase = sb + STAGES * STAGE_BYTES;
    const uint32_t qBase = sb + 2 * STAGES * STAGE_BYTES;

    const __nv_bfloat16* __restrict__ Ag = g_xs + (size_t)bm * KTOT;
    const __nv_bfloat16* __restrict__ Kg = g_ws + ((size_t)0 * NCOLS + bn) * KTOT;
    const __nv_bfloat16* __restrict__ Qg = g_ws + ((size_t)2 * NCOLS + bn) * KTOT;

    const int lrow0 = (tid)       >> 2, lcc0 = (tid)       & 3;
    const int lrow1 = (tid + 256) >> 2, lcc1 = (tid + 256) & 3;

    auto load_tile = [&](int kt, int s) {
        uint32_t as = aBase + s * STAGE_BYTES;
        uint32_t ks_ = kBase + s * STAGE_BYTES;
        uint32_t qs = qBase + s * STAGE_BYTES;
        const __nv_bfloat16* ak = Ag + kt * BK;
        const __nv_bfloat16* kk = Kg + kt * BK;
        const __nv_bfloat16* qk = Qg + kt * BK;
        cp_async16(as + lrow0 * ROWB + lcc0 * 16, ak + (size_t)lrow0 * KTOT + lcc0 * 8);
        cp_async16(as + lrow1 * ROWB + lcc1 * 16, ak + (size_t)lrow1 * KTOT + lcc1 * 8);
        cp_async16(ks_ + lrow0 * ROWB + lcc0 * 16, kk + (size_t)lrow0 * KTOT + lcc0 * 8);
        cp_async16(ks_ + lrow1 * ROWB + lcc1 * 16, kk + (size_t)lrow1 * KTOT + lcc1 * 8);
        cp_async16(qs + lrow0 * ROWB + lcc0 * 16, qk + (size_t)lrow0 * KTOT + lcc0 * 8);
        cp_async16(qs + lrow1 * ROWB + lcc1 * 16, qk + (size_t)lrow1 * KTOT + lcc1 * 8);
        cp_commit();
    };

    load_tile(0, 0);
    load_tile(1, 1);
    load_tile(2, 2);

    float accK[2][8][4], accQ[2][8][4];
#pragma unroll
    for (int mi = 0; mi < 2; mi++)
#pragma unroll
        for (int j = 0; j < 8; j++)
#pragma unroll
            for (int q = 0; q < 4; q++) { accK[mi][j][q] = 0.0f; accQ[mi][j][q] = 0.0f; }

    const int a_row  = wm * 32 + (lane & 15);
    const int a_byte = (lane >> 4) * 16;
    const int b_row  = wn * 64 + ((lane & 16) >> 1) + (lane & 7);
    const int b_byte = ((lane >> 3) & 1) * 16;

    for (int kt = 0; kt < NT; ++kt) {
        cp_wait2();
        __syncthreads();

        int nx = kt + STAGES - 1;
        if (nx < NT) load_tile(nx, nx % STAGES);
        else cp_commit();

        const int s = kt % STAGES;
        const uint32_t as = aBase + s * STAGE_BYTES;
        const uint32_t ks_ = kBase + s * STAGE_BYTES;
        const uint32_t qs = qBase + s * STAGE_BYTES;

#pragma unroll
        for (int ks2 = 0; ks2 < 2; ++ks2) {
            uint32_t a[2][4], b[4][4];
            ldsm_x4(a[0], as + (a_row)      * ROWB + ks2 * 32 + a_byte);
            ldsm_x4(a[1], as + (a_row + 16) * ROWB + ks2 * 32 + a_byte);
            // k operands + mma
#pragma unroll
            for (int jp = 0; jp < 4; jp++)
                ldsm_x4(b[jp], ks_ + (b_row + jp * 16) * ROWB + ks2 * 32 + b_byte);
#pragma unroll
            for (int mi = 0; mi < 2; mi++)
#pragma unroll
                for (int j = 0; j < 8; j++)
                    mma16816(accK[mi][j], a[mi], b[j >> 1][(j & 1) * 2], b[j >> 1][(j & 1) * 2 + 1]);
            // q operands + mma
#pragma unroll
            for (int jp = 0; jp < 4; jp++)
                ldsm_x4(b[jp], qs + (b_row + jp * 16) * ROWB + ks2 * 32 + b_byte);
#pragma unroll
            for (int mi = 0; mi < 2; mi++)
#pragma unroll
                for (int j = 0; j < 8; j++)
                    mma16816(accQ[mi][j], a[mi], b[j >> 1][(j & 1) * 2], b[j >> 1][(j & 1) * 2 + 1]);
        }
    }

    // epilogue: per-row dot over the head's 64 cols; warp wn owns one head
    const int h = blockIdx.x * 2 + wn;
    const int tr = lane >> 2;
#pragma unroll
    for (int mi = 0; mi < 2; mi++) {
        float p0 = 0.0f, p1 = 0.0f;
#pragma unroll
        for (int j = 0; j < 8; j++) {
            p0 += accK[mi][j][0] * accQ[mi][j][0] + accK[mi][j][1] * accQ[mi][j][1];
            p1 += accK[mi][j][2] * accQ[mi][j][2] + accK[mi][j][3] * accQ[mi][j][3];
        }
        p0 += __shfl_xor_sync(0xFFFFFFFF, p0, 1);
        p0 += __shfl_xor_sync(0xFFFFFFFF, p0, 2);
        p1 += __shfl_xor_sync(0xFFFFFFFF, p1, 1);
        p1 += __shfl_xor_sync(0xFFFFFFFF, p1, 2);
        if ((lane & 3) == 0) {
            int m0 = bm + wm * 32 + mi * 16 + tr;
            int b0 = m0 >> 11, t0 = m0 & (TLEN - 1);
            g_s[((size_t)(b0 * HEADS + h)) * TLEN + t0] = p0;
            int m1 = m0 + 8;
            int b1 = m1 >> 11, t1 = m1 & (TLEN - 1);
            g_s[((size_t)(b1 * HEADS + h)) * TLEN + t1] = p1;
        }
    }
}

// ---------------------------------------------------------------------------
// K1b: v GEMM (c=1) -> g_v fp32
// ---------------------------------------------------------------------------
__global__ __launch_bounds__(256, 2) void gemm_v_kernel() {
    extern __shared__ char smem[];
    const int tid = threadIdx.x;
    const int wid = tid >> 5;
    const int lane = tid & 31;

    const int bn = blockIdx.x * BN;
    const int bm = blockIdx.y * BM;
    const int wm = wid & 3;
    const int wn = wid >> 2;

    const uint32_t sb = smem_u32(smem);

    const __nv_bfloat16* __restrict__ Ag = g_xs + (size_t)bm * KTOT;
    const __nv_bfloat16* __restrict__ Bg = g_ws + ((size_t)1 * NCOLS + bn) * KTOT;

    const int lrow0 = (tid)       >> 2, lcc0 = (tid)       & 3;
    const int lrow1 = (tid + 256) >> 2, lcc1 = (tid + 256) & 3;

    auto load_tile = [&](int kt, int s) {
        uint32_t as = sb + s * STAGE_BYTES;
        uint32_t bs = sb + (STAGES + s) * STAGE_BYTES;
        const __nv_bfloat16* ak = Ag + kt * BK;
        const __nv_bfloat16* bk = Bg + kt * BK;
        cp_async16(as + lrow0 * ROWB + lcc0 * 16, ak + (size_t)lrow0 * KTOT + lcc0 * 8);
        cp_async16(as + lrow1 * ROWB + lcc1 * 16, ak + (size_t)lrow1 * KTOT + lcc1 * 8);
        cp_async16(bs + lrow0 * ROWB + lcc0 * 16, bk + (size_t)lrow0 * KTOT + lcc0 * 8);
        cp_async16(bs + lrow1 * ROWB + lcc1 * 16, bk + (size_t)lrow1 * KTOT + lcc1 * 8);
        cp_commit();
    };

    load_tile(0, 0);
    load_tile(1, 1);
    load_tile(2, 2);

    float acc[2][8][4];
#pragma unroll
    for (int mi = 0; mi < 2; mi++)
#pragma unroll
        for (int j = 0; j < 8; j++)
#pragma unroll
            for (int q = 0; q < 4; q++) acc[mi][j][q] = 0.0f;

    const int a_row  = wm * 32 + (lane & 15);
    const int a_byte = (lane >> 4) * 16;
    const int b_row  = wn * 64 + ((lane & 16) >> 1) + (lane & 7);
    const int b_byte = ((lane >> 3) & 1) * 16;

    for (int kt = 0; kt < NT; ++kt) {
        cp_wait2();
        __syncthreads();

        int nx = kt + STAGES - 1;
        if (nx < NT) load_tile(nx, nx % STAGES);
        else cp_commit();

        const int s = kt % STAGES;
        const uint32_t as = sb + s * STAGE_BYTES;
        const uint32_t bs = sb + (STAGES + s) * STAGE_BYTES;

#pragma unroll
        for (int ks = 0; ks < 2; ++ks) {
            uint32_t a[2][4], b[4][4];
            ldsm_x4(a[0], as + (a_row)      * ROWB + ks * 32 + a_byte);
            ldsm_x4(a[1], as + (a_row + 16) * ROWB + ks * 32 + a_byte);
#pragma unroll
            for (int jp = 0; jp < 4; jp++)
                ldsm_x4(b[jp], bs + (b_row + jp * 16) * ROWB + ks * 32 + b_byte);
#pragma unroll
            for (int mi = 0; mi < 2; mi++)
#pragma unroll
                for (int j = 0; j < 8; j++)
                    mma16816(acc[mi][j], a[mi], b[j >> 1][(j & 1) * 2], b[j >> 1][(j & 1) * 2 + 1]);
        }
    }

    const int tr = lane >> 2;
    const int tc = (lane & 3) * 2;
#pragma unroll
    for (int mi = 0; mi < 2; mi++) {
        int row0 = bm + wm * 32 + mi * 16 + tr;
#pragma unroll
        for (int j = 0; j < 8; j++) {
            int col = bn + wn * 64 + j * 8 + tc;
            *(float2*)(g_v + (size_t)row0 * NCOLS + col)       = make_float2(acc[mi][j][0], acc[mi][j][1]);
            *(float2*)(g_v + (size_t)(row0 + 8) * NCOLS + col) = make_float2(acc[mi][j][2], acc[mi][j][3]);
        }
    }
}

// ---------------------------------------------------------------------------
// K2: fused scan + head-sum. One CTA per batch b; warp = head; cross-head sum
//     accumulated in smem chunks (32 t x 64 d) and written directly to out.
// ---------------------------------------------------------------------------
#define CH 32
__global__ __launch_bounds__(512) void scanfuse_kernel(float* __restrict__ out) {
    const int b = blockIdx.x;
    const int wid = threadIdx.x >> 5;   // head
    const int lane = threadIdx.x & 31;
    const int tid = threadIdx.x;

    __shared__ float accbuf[CH][DDIM];  // 8 KB

    const float* __restrict__ vbase = g_v + (size_t)b * TLEN * NCOLS + wid * DDIM + 2 * lane;
    const float* __restrict__ sbase = g_s + ((size_t)(b * HEADS + wid)) * TLEN;
    float* __restrict__ outb = out + (size_t)b * TLEN * DDIM;

    float2 num = make_float2(0.0f, 0.0f);
    float den = 0.0f, mx = 0.0f;

    constexpr int PF = 8;
    float2 vbuf[PF];
    float sbuf[PF];
#pragma unroll
    for (int i = 0; i < PF; i++) {
        vbuf[i] = *(const float2*)(vbase + (size_t)i * NCOLS);
        sbuf[i] = sbase[i];
    }

    for (int t0 = 0; t0 < TLEN; t0 += CH) {
        // zero the chunk accumulator
        ((float4*)accbuf)[tid] = make_float4(0.0f, 0.0f, 0.0f, 0.0f);
        __syncthreads();

#pragma unroll
        for (int i = 0; i < CH; i++) {
            int t = t0 + i;
            int slot = t & (PF - 1);
            float2 vc = vbuf[slot];
            float sc = sbuf[slot];
            int tp = t + PF;
            if (tp < TLEN) {
                vbuf[slot] = *(const float2*)(vbase + (size_t)tp * NCOLS);
                sbuf[slot] = sbase[tp];
            }
            float nmx = fmaxf(mx, sc);
            float md = __expf(mx - nmx);
            float sm = __expf(sc - nmx);
            den = fmaf(den, md, sm);
            num.x = fmaf(num.x, md, vc.x * sm);
            num.y = fmaf(num.y, md, vc.y * sm);
            float inv = 1.0f / den;
            atomicAdd(&accbuf[i][2 * lane],     num.x * inv);
            atomicAdd(&accbuf[i][2 * lane + 1], num.y * inv);
            mx = nmx;
        }
        __syncthreads();

        // write chunk: 512 threads x float4 = 2048 floats
        ((float4*)(outb + (size_t)t0 * DDIM))[tid] = ((float4*)accbuf)[tid];
        __syncthreads();
    }
}

// ---------------------------------------------------------------------------
extern "C" void kernel_launch(void* const* d_in, const int* in_sizes, int n_in,
                              void* d_out, int out_size) {
    const float* x = (const float*)d_in[0];
    const float* w = (const float*)d_in[1];
    if (n_in >= 2 && in_sizes[0] == IDIM * HEADS * DDIM * 3) {
        const float* tmp = x; x = w; w = tmp;
    }
    float* out = (float*)d_out;

    {   // split conversions
        size_t tx = (size_t)MROWS * IDIM;
        convx_kernel<<<(unsigned)((tx + 255) / 256), 256>>>(x);
        size_t tw = 3ull * IDIM * NCOLS;
        convw_kernel<<<(unsigned)((tw + 255) / 256), 256>>>(w);
    }
    {   // fused k+q GEMM -> scores
        cudaFuncSetAttribute(gemm_kq_kernel, cudaFuncAttributeMaxDynamicSharedMemorySize, SMEM_KQ);
        dim3 grid(NCOLS / BN, MROWS / BM);
        gemm_kq_kernel<<<grid, 256, SMEM_KQ>>>();
    }
    {   // v GEMM
        cudaFuncSetAttribute(gemm_v_kernel, cudaFuncAttributeMaxDynamicSharedMemorySize, SMEM_V);
        dim3 grid(NCOLS / BN, MROWS / BM);
        gemm_v_kernel<<<grid, 256, SMEM_V>>>();
    }
    {   // fused scan + head reduction -> out
        scanfuse_kernel<<<BATCH, 512>>>(out);
    }
}

// round 5
// speedup vs baseline: 1.0562x; 1.0562x over previous
#include <cuda_runtime.h>
#include <cuda_bf16.h>
#include <cstdint>

// Problem dims
#define BATCH 32
#define TLEN  2048
#define IDIM  512
#define HEADS 16
#define DDIM  64
#define MROWS (BATCH * TLEN)      // 65536
#define NCOLS (HEADS * DDIM)      // 1024
#define KTOT  1536                // reduction length of split GEMM (3 segments)
#define KX    1024                // g_xs cols: [hi | lo]; segment 2 re-reads hi

// GEMM tiling
#define BM 128
#define BN 128                    // v kernel
#define BNH 64                    // kq kernel (one head)
#define BK 32
#define NT (KTOT / BK)            // 48
#define STAGES 5
#define ROWB 80                   // 32*2 + 16 pad (conflict-free ldmatrix)
#define V_STAGE  (2 * 128 * ROWB)         // 20480 (A + B)
#define KQ_STAGE ((128 + 64 + 64) * ROWB) // 20480 (A + Bk + Bq)
#define SMEM_V  (STAGES * V_STAGE)        // 102400
#define SMEM_KQ (STAGES * KQ_STAGE)       // 102400

// Scratch (device globals; allocation-free)
__device__ __nv_bfloat16 g_xs[(size_t)MROWS * KX];              // 128 MB split-X [m][hi|lo]
__device__ __nv_bfloat16 g_ws[3ull * NCOLS * KTOT];             // 9 MB split-W [c][n][k]
__device__ float g_v[(size_t)MROWS * NCOLS];                    // 256 MB v proj [m][n]
__device__ float g_s[(size_t)BATCH * HEADS * TLEN];             // 4 MB scores [bh][t]

// ---------------------------------------------------------------------------
// PTX helpers (family-portable)
// ---------------------------------------------------------------------------
__device__ __forceinline__ uint32_t smem_u32(const void* p) {
    uint32_t a;
    asm("{ .reg .u64 t; cvta.to.shared.u64 t, %1; cvt.u32.u64 %0, t; }" : "=r"(a) : "l"(p));
    return a;
}
__device__ __forceinline__ void cp_async16(uint32_t dst, const void* src) {
    asm volatile("cp.async.cg.shared.global [%0], [%1], 16;" :: "r"(dst), "l"(src));
}
__device__ __forceinline__ void cp_commit() { asm volatile("cp.async.commit_group;" ::: "memory"); }
__device__ __forceinline__ void cp_wait3()  { asm volatile("cp.async.wait_group 3;" ::: "memory"); }

__device__ __forceinline__ void ldsm_x4(uint32_t* r, uint32_t addr) {
    asm volatile("ldmatrix.sync.aligned.m8n8.x4.shared.b16 {%0,%1,%2,%3}, [%4];"
                 : "=r"(r[0]), "=r"(r[1]), "=r"(r[2]), "=r"(r[3]) : "r"(addr));
}
__device__ __forceinline__ void mma16816(float* c, const uint32_t* a, uint32_t b0, uint32_t b1) {
    asm volatile("mma.sync.aligned.m16n8k16.row.col.f32.bf16.bf16.f32 "
                 "{%0,%1,%2,%3}, {%4,%5,%6,%7}, {%8,%9}, {%0,%1,%2,%3};"
                 : "+f"(c[0]), "+f"(c[1]), "+f"(c[2]), "+f"(c[3])
                 : "r"(a[0]), "r"(a[1]), "r"(a[2]), "r"(a[3]), "r"(b0), "r"(b1));
}

// A-tile source column for reduction chunk kt (hi reuse in segment 2)
__device__ __forceinline__ int a_src_col(int kt) { return (kt < 32 ? kt : kt - 32) * BK; }

// ---------------------------------------------------------------------------
// K0a: split X -> bf16 [hi | lo]
// ---------------------------------------------------------------------------
__global__ void convx_kernel(const float* __restrict__ x) {
    size_t e = (size_t)blockIdx.x * blockDim.x + threadIdx.x;
    if (e >= (size_t)MROWS * IDIM) return;
    size_t m = e >> 9;
    int k = (int)(e & 511);
    float v = x[e];
    __nv_bfloat16 hi = __float2bfloat16(v);
    __nv_bfloat16 lo = __float2bfloat16(v - __bfloat162float(hi));
    __nv_bfloat16* row = g_xs + m * KX;
    row[k] = hi;
    row[512 + k] = lo;
}

// ---------------------------------------------------------------------------
// K0b: split W -> Ws[c][n][0:512)=hi, [512:1024)=hi, [1024:1536)=lo
//      (pairs with X segments: hi·hi + lo·hi + hi·lo)
// ---------------------------------------------------------------------------
__global__ void convw_kernel(const float* __restrict__ W) {
    size_t e = (size_t)blockIdx.x * blockDim.x + threadIdx.x;
    if (e >= 3ull * IDIM * NCOLS) return;
    int c = (int)(e / (IDIM * NCOLS));
    int r = (int)(e % (IDIM * NCOLS));
    int k = r >> 10;
    int n = r & 1023;
    int h = n >> 6, d = n & 63;
    float v = W[(size_t)k * (HEADS * DDIM * 3) + h * (DDIM * 3) + d * 3 + c];
    __nv_bfloat16 hi = __float2bfloat16(v);
    __nv_bfloat16 lo = __float2bfloat16(v - __bfloat162float(hi));
    __nv_bfloat16* base = g_ws + ((size_t)c * NCOLS + n) * KTOT;
    base[k] = hi;
    base[512 + k] = hi;
    base[1024 + k] = lo;
}

// ---------------------------------------------------------------------------
// K1a: fused k+q GEMM -> scores. One head per CTA (BN=64), dual 32x32 warp
//      tiles, 5-stage cp.async, 2 CTAs/SM. Scores reduced in smem.
// ---------------------------------------------------------------------------
__global__ __launch_bounds__(256, 2) void gemm_kq_kernel() {
    extern __shared__ char smem[];
    __shared__ float sred[BM];

    const int tid = threadIdx.x;
    const int wid = tid >> 5;
    const int lane = tid & 31;

    const int h = blockIdx.x;                    // head
    const int bm = blockIdx.y * BM;
    const int wm = wid & 3;
    const int wn = wid >> 2;                     // 0,1: column half

    const uint32_t sb = smem_u32(smem);

    const __nv_bfloat16* __restrict__ Ag = g_xs + (size_t)bm * KX;
    const __nv_bfloat16* __restrict__ Kg = g_ws + ((size_t)0 * NCOLS + h * BNH) * KTOT;
    const __nv_bfloat16* __restrict__ Qg = g_ws + ((size_t)2 * NCOLS + h * BNH) * KTOT;

    // loader coords
    const int ar0 = (tid)       >> 2, ac0 = (tid)       & 3;
    const int ar1 = (tid + 256) >> 2, ac1 = (tid + 256) & 3;
    const int br  = tid >> 2,         bc  = tid & 3;      // 64 rows

    auto load_tile = [&](int kt, int s) {
        uint32_t aS = sb + s * KQ_STAGE;
        uint32_t kS = aS + 128 * ROWB;
        uint32_t qS = aS + 192 * ROWB;
        const __nv_bfloat16* ag = Ag + a_src_col(kt);
        const __nv_bfloat16* kg = Kg + kt * BK;
        const __nv_bfloat16* qg = Qg + kt * BK;
        cp_async16(aS + ar0 * ROWB + ac0 * 16, ag + (size_t)ar0 * KX + ac0 * 8);
        cp_async16(aS + ar1 * ROWB + ac1 * 16, ag + (size_t)ar1 * KX + ac1 * 8);
        cp_async16(kS + br * ROWB + bc * 16, kg + (size_t)br * KTOT + bc * 8);
        cp_async16(qS + br * ROWB + bc * 16, qg + (size_t)br * KTOT + bc * 8);
        cp_commit();
    };

    load_tile(0, 0);
    load_tile(1, 1);
    load_tile(2, 2);
    load_tile(3, 3);

    float accK[2][4][4], accQ[2][4][4];
#pragma unroll
    for (int mi = 0; mi < 2; mi++)
#pragma unroll
        for (int j = 0; j < 4; j++)
#pragma unroll
            for (int q = 0; q < 4; q++) { accK[mi][j][q] = 0.0f; accQ[mi][j][q] = 0.0f; }

    const int a_row  = wm * 32 + (lane & 15);
    const int a_byte = (lane >> 4) * 16;
    const int b_row  = wn * 32 + ((lane & 16) >> 1) + (lane & 7);
    const int b_byte = ((lane >> 3) & 1) * 16;

    for (int kt = 0; kt < NT; ++kt) {
        cp_wait3();
        __syncthreads();

        int nx = kt + STAGES - 1;
        if (nx < NT) load_tile(nx, nx % STAGES);
        else cp_commit();

        const int s = kt % STAGES;
        const uint32_t aS = sb + s * KQ_STAGE;
        const uint32_t kS = aS + 128 * ROWB;
        const uint32_t qS = aS + 192 * ROWB;

#pragma unroll
        for (int ks = 0; ks < 2; ++ks) {
            uint32_t a[2][4], bk[2][4], bq[2][4];
            ldsm_x4(a[0], aS + (a_row)      * ROWB + ks * 32 + a_byte);
            ldsm_x4(a[1], aS + (a_row + 16) * ROWB + ks * 32 + a_byte);
            ldsm_x4(bk[0], kS + (b_row)      * ROWB + ks * 32 + b_byte);
            ldsm_x4(bk[1], kS + (b_row + 16) * ROWB + ks * 32 + b_byte);
            ldsm_x4(bq[0], qS + (b_row)      * ROWB + ks * 32 + b_byte);
            ldsm_x4(bq[1], qS + (b_row + 16) * ROWB + ks * 32 + b_byte);
#pragma unroll
            for (int mi = 0; mi < 2; mi++)
#pragma unroll
                for (int j = 0; j < 4; j++) {
                    mma16816(accK[mi][j], a[mi], bk[j >> 1][(j & 1) * 2], bk[j >> 1][(j & 1) * 2 + 1]);
                    mma16816(accQ[mi][j], a[mi], bq[j >> 1][(j & 1) * 2], bq[j >> 1][(j & 1) * 2 + 1]);
                }
        }
    }

    // epilogue: s[row] = sum over head's 64 cols of k*q
    if (tid < BM) sred[tid] = 0.0f;
    __syncthreads();

    const int tr = lane >> 2;
#pragma unroll
    for (int mi = 0; mi < 2; mi++) {
        float p0 = 0.0f, p1 = 0.0f;
#pragma unroll
        for (int j = 0; j < 4; j++) {
            p0 += accK[mi][j][0] * accQ[mi][j][0] + accK[mi][j][1] * accQ[mi][j][1];
            p1 += accK[mi][j][2] * accQ[mi][j][2] + accK[mi][j][3] * accQ[mi][j][3];
        }
        p0 += __shfl_xor_sync(0xFFFFFFFF, p0, 1);
        p0 += __shfl_xor_sync(0xFFFFFFFF, p0, 2);
        p1 += __shfl_xor_sync(0xFFFFFFFF, p1, 1);
        p1 += __shfl_xor_sync(0xFFFFFFFF, p1, 2);
        if ((lane & 3) == 0) {
            atomicAdd(&sred[wm * 32 + mi * 16 + tr], p0);
            atomicAdd(&sred[wm * 32 + mi * 16 + tr + 8], p1);
        }
    }
    __syncthreads();

    if (tid < BM) {
        int m = bm + tid;
        int b = m >> 11, t = m & (TLEN - 1);
        g_s[((size_t)(b * HEADS + h)) * TLEN + t] = sred[tid];
    }
}

// ---------------------------------------------------------------------------
// K1b: v GEMM -> g_v fp32 (128x128 tiles, 5-stage)
// ---------------------------------------------------------------------------
__global__ __launch_bounds__(256, 2) void gemm_v_kernel() {
    extern __shared__ char smem[];
    const int tid = threadIdx.x;
    const int wid = tid >> 5;
    const int lane = tid & 31;

    const int bn = blockIdx.x * BN;
    const int bm = blockIdx.y * BM;
    const int wm = wid & 3;
    const int wn = wid >> 2;

    const uint32_t sb = smem_u32(smem);

    const __nv_bfloat16* __restrict__ Ag = g_xs + (size_t)bm * KX;
    const __nv_bfloat16* __restrict__ Bg = g_ws + ((size_t)1 * NCOLS + bn) * KTOT;

    const int lrow0 = (tid)       >> 2, lcc0 = (tid)       & 3;
    const int lrow1 = (tid + 256) >> 2, lcc1 = (tid + 256) & 3;

    auto load_tile = [&](int kt, int s) {
        uint32_t as = sb + s * V_STAGE;
        uint32_t bs = as + 128 * ROWB;
        const __nv_bfloat16* ak = Ag + a_src_col(kt);
        const __nv_bfloat16* bk = Bg + kt * BK;
        cp_async16(as + lrow0 * ROWB + lcc0 * 16, ak + (size_t)lrow0 * KX + lcc0 * 8);
        cp_async16(as + lrow1 * ROWB + lcc1 * 16, ak + (size_t)lrow1 * KX + lcc1 * 8);
        cp_async16(bs + lrow0 * ROWB + lcc0 * 16, bk + (size_t)lrow0 * KTOT + lcc0 * 8);
        cp_async16(bs + lrow1 * ROWB + lcc1 * 16, bk + (size_t)lrow1 * KTOT + lcc1 * 8);
        cp_commit();
    };

    load_tile(0, 0);
    load_tile(1, 1);
    load_tile(2, 2);
    load_tile(3, 3);

    float acc[2][8][4];
#pragma unroll
    for (int mi = 0; mi < 2; mi++)
#pragma unroll
        for (int j = 0; j < 8; j++)
#pragma unroll
            for (int q = 0; q < 4; q++) acc[mi][j][q] = 0.0f;

    const int a_row  = wm * 32 + (lane & 15);
    const int a_byte = (lane >> 4) * 16;
    const int b_row  = wn * 64 + ((lane & 16) >> 1) + (lane & 7);
    const int b_byte = ((lane >> 3) & 1) * 16;

    for (int kt = 0; kt < NT; ++kt) {
        cp_wait3();
        __syncthreads();

        int nx = kt + STAGES - 1;
        if (nx < NT) load_tile(nx, nx % STAGES);
        else cp_commit();

        const int s = kt % STAGES;
        const uint32_t as = sb + s * V_STAGE;
        const uint32_t bs = as + 128 * ROWB;

#pragma unroll
        for (int ks = 0; ks < 2; ++ks) {
            uint32_t a[2][4], b[4][4];
            ldsm_x4(a[0], as + (a_row)      * ROWB + ks * 32 + a_byte);
            ldsm_x4(a[1], as + (a_row + 16) * ROWB + ks * 32 + a_byte);
#pragma unroll
            for (int jp = 0; jp < 4; jp++)
                ldsm_x4(b[jp], bs + (b_row + jp * 16) * ROWB + ks * 32 + b_byte);
#pragma unroll
            for (int mi = 0; mi < 2; mi++)
#pragma unroll
                for (int j = 0; j < 8; j++)
                    mma16816(acc[mi][j], a[mi], b[j >> 1][(j & 1) * 2], b[j >> 1][(j & 1) * 2 + 1]);
        }
    }

    const int tr = lane >> 2;
    const int tc = (lane & 3) * 2;
#pragma unroll
    for (int mi = 0; mi < 2; mi++) {
        int row0 = bm + wm * 32 + mi * 16 + tr;
#pragma unroll
        for (int j = 0; j < 8; j++) {
            int col = bn + wn * 64 + j * 8 + tc;
            *(float2*)(g_v + (size_t)row0 * NCOLS + col)       = make_float2(acc[mi][j][0], acc[mi][j][1]);
            *(float2*)(g_v + (size_t)(row0 + 8) * NCOLS + col) = make_float2(acc[mi][j][2], acc[mi][j][3]);
        }
    }
}

// ---------------------------------------------------------------------------
// K2: fused scan + head-sum. One CTA per batch; warp = head; cross-head sums
//     accumulated in smem chunks (32 t x 64 d), written directly to out.
// ---------------------------------------------------------------------------
#define CH 32
__global__ __launch_bounds__(512) void scanfuse_kernel(float* __restrict__ out) {
    const int b = blockIdx.x;
    const int wid = threadIdx.x >> 5;   // head
    const int lane = threadIdx.x & 31;
    const int tid = threadIdx.x;

    __shared__ float accbuf[CH][DDIM];  // 8 KB

    const float* __restrict__ vbase = g_v + (size_t)b * TLEN * NCOLS + wid * DDIM + 2 * lane;
    const float* __restrict__ sbase = g_s + ((size_t)(b * HEADS + wid)) * TLEN;
    float* __restrict__ outb = out + (size_t)b * TLEN * DDIM;

    float2 num = make_float2(0.0f, 0.0f);
    float den = 0.0f, mx = 0.0f;

    constexpr int PF = 8;
    float2 vbuf[PF];
    float sbuf[PF];
#pragma unroll
    for (int i = 0; i < PF; i++) {
        vbuf[i] = *(const float2*)(vbase + (size_t)i * NCOLS);
        sbuf[i] = sbase[i];
    }

    for (int t0 = 0; t0 < TLEN; t0 += CH) {
        ((float4*)accbuf)[tid] = make_float4(0.0f, 0.0f, 0.0f, 0.0f);
        __syncthreads();

#pragma unroll
        for (int i = 0; i < CH; i++) {
            int t = t0 + i;
            int slot = t & (PF - 1);
            float2 vc = vbuf[slot];
            float sc = sbuf[slot];
            int tp = t + PF;
            if (tp < TLEN) {
                vbuf[slot] = *(const float2*)(vbase + (size_t)tp * NCOLS);
                sbuf[slot] = sbase[tp];
            }
            float nmx = fmaxf(mx, sc);
            float md = __expf(mx - nmx);
            float sm = __expf(sc - nmx);
            den = fmaf(den, md, sm);
            num.x = fmaf(num.x, md, vc.x * sm);
            num.y = fmaf(num.y, md, vc.y * sm);
            float inv = 1.0f / den;
            atomicAdd(&accbuf[i][2 * lane],     num.x * inv);
            atomicAdd(&accbuf[i][2 * lane + 1], num.y * inv);
            mx = nmx;
        }
        __syncthreads();

        ((float4*)(outb + (size_t)t0 * DDIM))[tid] = ((float4*)accbuf)[tid];
        __syncthreads();
    }
}

// ---------------------------------------------------------------------------
extern "C" void kernel_launch(void* const* d_in, const int* in_sizes, int n_in,
                              void* d_out, int out_size) {
    const float* x = (const float*)d_in[0];
    const float* w = (const float*)d_in[1];
    if (n_in >= 2 && in_sizes[0] == IDIM * HEADS * DDIM * 3) {
        const float* tmp = x; x = w; w = tmp;
    }
    float* out = (float*)d_out;

    {   // split conversions
        size_t tx = (size_t)MROWS * IDIM;
        convx_kernel<<<(unsigned)((tx + 255) / 256), 256>>>(x);
        size_t tw = 3ull * IDIM * NCOLS;
        convw_kernel<<<(unsigned)((tw + 255) / 256), 256>>>(w);
    }
    {   // fused k+q GEMM -> scores
        cudaFuncSetAttribute(gemm_kq_kernel, cudaFuncAttributeMaxDynamicSharedMemorySize, SMEM_KQ);
        dim3 grid(HEADS, MROWS / BM);
        gemm_kq_kernel<<<grid, 256, SMEM_KQ>>>();
    }
    {   // v GEMM
        cudaFuncSetAttribute(gemm_v_kernel, cudaFuncAttributeMaxDynamicSharedMemorySize, SMEM_V);
        dim3 grid(NCOLS / BN, MROWS / BM);
        gemm_v_kernel<<<grid, 256, SMEM_V>>>();
    }
    {   // fused scan + head reduction -> out
        scanfuse_kernel<<<BATCH, 512>>>(out);
    }
}

// round 6
// speedup vs baseline: 1.3051x; 1.2357x over previous
#include <cuda_runtime.h>
#include <cuda_bf16.h>
#include <cstdint>

// Problem dims
#define BATCH 32
#define TLEN  2048
#define IDIM  512
#define HEADS 16
#define DDIM  64
#define MROWS (BATCH * TLEN)      // 65536
#define NCOLS (HEADS * DDIM)      // 1024
#define KTOT  1536                // split-GEMM reduction (3 segments)
#define KX    1024                // g_xs cols [hi|lo]; segment 2 re-reads hi

// GEMM tiling: 128x128 CTA tile, 4 warps of 64x64, BK=32, 5 stages
#define BM 128
#define BK 32
#define NT (KTOT / BK)            // 48
#define STAGES 5
#define ROWB 80                   // 32*2 + 16 pad (conflict-free ldmatrix)
#define STAGE_B (2 * 128 * ROWB)  // 20480 (A + B)
#define SMEM_GEMM (STAGES * STAGE_B)  // 102400

// Scan chunking
#define NCH 8
#define CL  (TLEN / NCH)          // 256
#define CH  32

// Scratch (device globals; allocation-free)
__device__ __nv_bfloat16 g_xs[(size_t)MROWS * KX];              // 128 MB split-X
__device__ __nv_bfloat16 g_wv[(size_t)NCOLS * KTOT];            // 3 MB  W_v   [n][k]
__device__ __nv_bfloat16 g_wkq[(size_t)2 * NCOLS * KTOT];       // 6 MB  W_kq  [h*128 + (k|q)][k]
__device__ float g_v[(size_t)MROWS * NCOLS];                    // 256 MB v proj
__device__ float g_s[(size_t)BATCH * HEADS * TLEN];             // 4 MB scores
__device__ float g_agg[(size_t)BATCH * HEADS * NCH * 68];       // 1.1 MB chunk aggregates

// ---------------------------------------------------------------------------
// PTX helpers (family-portable)
// ---------------------------------------------------------------------------
__device__ __forceinline__ uint32_t smem_u32(const void* p) {
    uint32_t a;
    asm("{ .reg .u64 t; cvta.to.shared.u64 t, %1; cvt.u32.u64 %0, t; }" : "=r"(a) : "l"(p));
    return a;
}
__device__ __forceinline__ void cp_async16(uint32_t dst, const void* src) {
    asm volatile("cp.async.cg.shared.global [%0], [%1], 16;" :: "r"(dst), "l"(src));
}
__device__ __forceinline__ void cp_commit() { asm volatile("cp.async.commit_group;" ::: "memory"); }
__device__ __forceinline__ void cp_wait3()  { asm volatile("cp.async.wait_group 3;" ::: "memory"); }
__device__ __forceinline__ void cp_wait0()  { asm volatile("cp.async.wait_group 0;" ::: "memory"); }

__device__ __forceinline__ void ldsm_x4(uint32_t* r, uint32_t addr) {
    asm volatile("ldmatrix.sync.aligned.m8n8.x4.shared.b16 {%0,%1,%2,%3}, [%4];"
                 : "=r"(r[0]), "=r"(r[1]), "=r"(r[2]), "=r"(r[3]) : "r"(addr));
}
__device__ __forceinline__ void mma16816(float* c, const uint32_t* a, uint32_t b0, uint32_t b1) {
    asm volatile("mma.sync.aligned.m16n8k16.row.col.f32.bf16.bf16.f32 "
                 "{%0,%1,%2,%3}, {%4,%5,%6,%7}, {%8,%9}, {%0,%1,%2,%3};"
                 : "+f"(c[0]), "+f"(c[1]), "+f"(c[2]), "+f"(c[3])
                 : "r"(a[0]), "r"(a[1]), "r"(a[2]), "r"(a[3]), "r"(b0), "r"(b1));
}

// A-tile source column for reduction chunk kt (hi reuse in segment 2)
__device__ __forceinline__ int a_src_col(int kt) { return (kt < 32 ? kt : kt - 32) * BK; }

// ---------------------------------------------------------------------------
// K0a: split X -> bf16 [hi | lo]
// ---------------------------------------------------------------------------
__global__ void convx_kernel(const float* __restrict__ x) {
    size_t e = (size_t)blockIdx.x * blockDim.x + threadIdx.x;
    if (e >= (size_t)MROWS * IDIM) return;
    size_t m = e >> 9;
    int k = (int)(e & 511);
    float v = x[e];
    __nv_bfloat16 hi = __float2bfloat16(v);
    __nv_bfloat16 lo = __float2bfloat16(v - __bfloat162float(hi));
    __nv_bfloat16* row = g_xs + m * KX;
    row[k] = hi;
    row[512 + k] = lo;
}

// ---------------------------------------------------------------------------
// K0b: split W. Segments per row: [0:512)=hi, [512:1024)=hi, [1024:1536)=lo
//      c=1 -> g_wv[n][.]; c=0 -> g_wkq[h*128+d][.]; c=2 -> g_wkq[h*128+64+d][.]
// ---------------------------------------------------------------------------
__global__ void convw_kernel(const float* __restrict__ W) {
    size_t e = (size_t)blockIdx.x * blockDim.x + threadIdx.x;
    if (e >= 3ull * IDIM * NCOLS) return;
    int c = (int)(e / (IDIM * NCOLS));
    int r = (int)(e % (IDIM * NCOLS));
    int k = r >> 10;
    int n = r & 1023;
    int h = n >> 6, d = n & 63;
    float v = W[(size_t)k * (HEADS * DDIM * 3) + h * (DDIM * 3) + d * 3 + c];
    __nv_bfloat16 hi = __float2bfloat16(v);
    __nv_bfloat16 lo = __float2bfloat16(v - __bfloat162float(hi));
    __nv_bfloat16* base;
    if (c == 1)      base = g_wv + (size_t)n * KTOT;
    else if (c == 0) base = g_wkq + ((size_t)h * 128 + d) * KTOT;
    else             base = g_wkq + ((size_t)h * 128 + 64 + d) * KTOT;
    base[k] = hi;
    base[512 + k] = hi;
    base[1024 + k] = lo;
}

// ---------------------------------------------------------------------------
// K1: unified GEMM. grid.x: 0..7 -> v n-block; 8..23 -> head (kq interleaved).
//     128x128 CTA tile, 4 warps (2m x 2n) of 64x64, 5-stage cp.async.
//     kq epilogue: k-warps dump to smem, q-warps form scores.
// ---------------------------------------------------------------------------
__global__ __launch_bounds__(128, 2) void gemm_kernel() {
    extern __shared__ char smem[];
    const int tid = threadIdx.x;
    const int wid = tid >> 5;
    const int lane = tid & 31;

    const int bx = blockIdx.x;
    const int bm = blockIdx.y * BM;
    const int wm = wid & 1;
    const int wn = wid >> 1;
    const bool is_v = (bx < 8);

    const uint32_t sb = smem_u32(smem);

    const __nv_bfloat16* __restrict__ Ag = g_xs + (size_t)bm * KX;
    const __nv_bfloat16* __restrict__ Bg = is_v
        ? g_wv + (size_t)bx * 128 * KTOT
        : g_wkq + (size_t)(bx - 8) * 128 * KTOT;

    auto load_tile = [&](int kt, int s) {
        uint32_t aS = sb + s * STAGE_B;
        uint32_t bS = aS + 128 * ROWB;
        const __nv_bfloat16* ag = Ag + a_src_col(kt);
        const __nv_bfloat16* bg = Bg + kt * BK;
#pragma unroll
        for (int i = 0; i < 4; i++) {
            int idx = tid + i * 128;
            int row = idx >> 2, cc = idx & 3;
            cp_async16(aS + row * ROWB + cc * 16, ag + (size_t)row * KX + cc * 8);
        }
#pragma unroll
        for (int i = 0; i < 4; i++) {
            int idx = tid + i * 128;
            int row = idx >> 2, cc = idx & 3;
            cp_async16(bS + row * ROWB + cc * 16, bg + (size_t)row * KTOT + cc * 8);
        }
        cp_commit();
    };

    load_tile(0, 0);
    load_tile(1, 1);
    load_tile(2, 2);
    load_tile(3, 3);

    float acc[4][8][4];
#pragma unroll
    for (int mi = 0; mi < 4; mi++)
#pragma unroll
        for (int j = 0; j < 8; j++)
#pragma unroll
            for (int q = 0; q < 4; q++) acc[mi][j][q] = 0.0f;

    const int a_row  = wm * 64 + (lane & 15);
    const int a_byte = (lane >> 4) * 16;
    const int b_row  = wn * 64 + ((lane & 16) >> 1) + (lane & 7);
    const int b_byte = ((lane >> 3) & 1) * 16;

    for (int kt = 0; kt < NT; ++kt) {
        cp_wait3();
        __syncthreads();

        int nx = kt + STAGES - 1;
        if (nx < NT) load_tile(nx, nx % STAGES);
        else cp_commit();

        const int s = kt % STAGES;
        const uint32_t aS = sb + s * STAGE_B;
        const uint32_t bS = aS + 128 * ROWB;

#pragma unroll
        for (int ks = 0; ks < 2; ++ks) {
            uint32_t a[4][4], b[4][4];
#pragma unroll
            for (int mi = 0; mi < 4; mi++)
                ldsm_x4(a[mi], aS + (a_row + 16 * mi) * ROWB + ks * 32 + a_byte);
#pragma unroll
            for (int jp = 0; jp < 4; jp++)
                ldsm_x4(b[jp], bS + (b_row + 16 * jp) * ROWB + ks * 32 + b_byte);
#pragma unroll
            for (int mi = 0; mi < 4; mi++)
#pragma unroll
                for (int j = 0; j < 8; j++)
                    mma16816(acc[mi][j], a[mi], b[j >> 1][(j & 1) * 2], b[j >> 1][(j & 1) * 2 + 1]);
        }
    }

    // drain async copies (smem may be reused below)
    cp_wait0();
    __syncthreads();

    const int tr = lane >> 2;
    const int tc = (lane & 3) * 2;

    if (is_v) {
        const int bn = bx * 128;
#pragma unroll
        for (int mi = 0; mi < 4; mi++) {
            int row0 = bm + wm * 64 + mi * 16 + tr;
#pragma unroll
            for (int j = 0; j < 8; j++) {
                int col = bn + wn * 64 + j * 8 + tc;
                *(float2*)(g_v + (size_t)row0 * NCOLS + col)       = make_float2(acc[mi][j][0], acc[mi][j][1]);
                *(float2*)(g_v + (size_t)(row0 + 8) * NCOLS + col) = make_float2(acc[mi][j][2], acc[mi][j][3]);
            }
        }
    } else {
        const int h = bx - 8;
        float* sk = (float*)smem;   // 128 x 65 exchange buffer (aliases pipeline smem)
        if (wn == 0) {
#pragma unroll
            for (int mi = 0; mi < 4; mi++) {
                int row = wm * 64 + mi * 16 + tr;
#pragma unroll
                for (int j = 0; j < 8; j++) {
                    int col = j * 8 + tc;
                    sk[row * 65 + col]           = acc[mi][j][0];
                    sk[row * 65 + col + 1]       = acc[mi][j][1];
                    sk[(row + 8) * 65 + col]     = acc[mi][j][2];
                    sk[(row + 8) * 65 + col + 1] = acc[mi][j][3];
                }
            }
        }
        __syncthreads();
        if (wn == 1) {
#pragma unroll
            for (int mi = 0; mi < 4; mi++) {
                int row = wm * 64 + mi * 16 + tr;
                float p0 = 0.0f, p1 = 0.0f;
#pragma unroll
                for (int j = 0; j < 8; j++) {
                    int col = j * 8 + tc;
                    p0 += acc[mi][j][0] * sk[row * 65 + col] + acc[mi][j][1] * sk[row * 65 + col + 1];
                    p1 += acc[mi][j][2] * sk[(row + 8) * 65 + col] + acc[mi][j][3] * sk[(row + 8) * 65 + col + 1];
                }
                p0 += __shfl_xor_sync(0xFFFFFFFF, p0, 1);
                p0 += __shfl_xor_sync(0xFFFFFFFF, p0, 2);
                p1 += __shfl_xor_sync(0xFFFFFFFF, p1, 1);
                p1 += __shfl_xor_sync(0xFFFFFFFF, p1, 2);
                if ((lane & 3) == 0) {
                    int m0 = bm + row;
                    int b0 = m0 >> 11, t0 = m0 & (TLEN - 1);
                    g_s[((size_t)(b0 * HEADS + h)) * TLEN + t0] = p0;
                    int m1 = m0 + 8;
                    int b1 = m1 >> 11, t1 = m1 & (TLEN - 1);
                    g_s[((size_t)(b1 * HEADS + h)) * TLEN + t1] = p1;
                }
            }
        }
    }
}

// ---------------------------------------------------------------------------
// K2a: scan phase A — per-chunk aggregates (chunks 0..NCH-2), no outputs.
// ---------------------------------------------------------------------------
__global__ __launch_bounds__(512) void scanA_kernel() {
    const int b = blockIdx.x;
    const int c = blockIdx.y;           // 0..NCH-2
    const int wid = threadIdx.x >> 5;   // head
    const int lane = threadIdx.x & 31;
    const int bh = b * HEADS + wid;

    const float* __restrict__ vbase =
        g_v + ((size_t)b * TLEN + c * CL) * NCOLS + wid * DDIM + 2 * lane;
    const float* __restrict__ sbase = g_s + (size_t)bh * TLEN + c * CL;

    float2 num = make_float2(0.0f, 0.0f);
    float den = 0.0f, mx = 0.0f;

    constexpr int PF = 8;
    float2 vbuf[PF];
    float sbuf[PF];
#pragma unroll
    for (int i = 0; i < PF; i++) {
        vbuf[i] = *(const float2*)(vbase + (size_t)i * NCOLS);
        sbuf[i] = sbase[i];
    }

    for (int t = 0; t < CL; ++t) {
        int slot = t & (PF - 1);
        float2 vc = vbuf[slot];
        float sc = sbuf[slot];
        int tp = t + PF;
        if (tp < CL) {
            vbuf[slot] = *(const float2*)(vbase + (size_t)tp * NCOLS);
            sbuf[slot] = sbase[tp];
        }
        float nmx = fmaxf(mx, sc);
        float md = __expf(mx - nmx);
        float sm = __expf(sc - nmx);
        den = fmaf(den, md, sm);
        num.x = fmaf(num.x, md, vc.x * sm);
        num.y = fmaf(num.y, md, vc.y * sm);
        mx = nmx;
    }

    float* ag = g_agg + ((size_t)bh * NCH + c) * 68;
    ag[2 * lane] = num.x;
    ag[2 * lane + 1] = num.y;
    if (lane == 0) { ag[64] = den; ag[65] = mx; }
}

// ---------------------------------------------------------------------------
// K2b: scan phase B — fold carry from aggregates, scan own chunk, head-sum
//      via smem atomics, write output directly.
// ---------------------------------------------------------------------------
__global__ __launch_bounds__(512) void scanB_kernel(float* __restrict__ out) {
    const int b = blockIdx.x;
    const int c = blockIdx.y;           // 0..NCH-1
    const int wid = threadIdx.x >> 5;   // head
    const int lane = threadIdx.x & 31;
    const int tid = threadIdx.x;
    const int bh = b * HEADS + wid;

    __shared__ float accbuf[CH][DDIM];

    const float* __restrict__ vbase = g_v + (size_t)b * TLEN * NCOLS + wid * DDIM + 2 * lane;
    const float* __restrict__ sbase = g_s + (size_t)bh * TLEN;
    float* __restrict__ outb = out + (size_t)b * TLEN * DDIM;

    float2 num = make_float2(0.0f, 0.0f);
    float den = 0.0f, mx = 0.0f;

    // fold prefix aggregates
    for (int cc = 0; cc < c; ++cc) {
        const float* ag = g_agg + ((size_t)bh * NCH + cc) * 68;
        float anx = ag[2 * lane], any_ = ag[2 * lane + 1];
        float ad = ag[64], am = ag[65];
        float nmx = fmaxf(mx, am);
        float e1 = __expf(mx - nmx);
        float e2 = __expf(am - nmx);
        den = den * e1 + ad * e2;
        num.x = num.x * e1 + anx * e2;
        num.y = num.y * e1 + any_ * e2;
        mx = nmx;
    }

    const int tlo = c * CL;
    constexpr int PF = 8;
    float2 vbuf[PF];
    float sbuf[PF];
#pragma unroll
    for (int i = 0; i < PF; i++) {
        vbuf[i] = *(const float2*)(vbase + (size_t)(tlo + i) * NCOLS);
        sbuf[i] = sbase[tlo + i];
    }

    for (int t0 = tlo; t0 < tlo + CL; t0 += CH) {
        ((float4*)accbuf)[tid] = make_float4(0.0f, 0.0f, 0.0f, 0.0f);
        __syncthreads();

#pragma unroll
        for (int i = 0; i < CH; i++) {
            int t = t0 + i;
            int slot = t & (PF - 1);
            float2 vc = vbuf[slot];
            float sc = sbuf[slot];
            int tp = t + PF;
            if (tp < TLEN) {
                vbuf[slot] = *(const float2*)(vbase + (size_t)tp * NCOLS);
                sbuf[slot] = sbase[tp];
            }
            float nmx = fmaxf(mx, sc);
            float md = __expf(mx - nmx);
            float sm = __expf(sc - nmx);
            den = fmaf(den, md, sm);
            num.x = fmaf(num.x, md, vc.x * sm);
            num.y = fmaf(num.y, md, vc.y * sm);
            float inv = 1.0f / den;
            atomicAdd(&accbuf[i][2 * lane],     num.x * inv);
            atomicAdd(&accbuf[i][2 * lane + 1], num.y * inv);
            mx = nmx;
        }
        __syncthreads();

        ((float4*)(outb + (size_t)t0 * DDIM))[tid] = ((float4*)accbuf)[tid];
        __syncthreads();
    }
}

// ---------------------------------------------------------------------------
extern "C" void kernel_launch(void* const* d_in, const int* in_sizes, int n_in,
                              void* d_out, int out_size) {
    const float* x = (const float*)d_in[0];
    const float* w = (const float*)d_in[1];
    if (n_in >= 2 && in_sizes[0] == IDIM * HEADS * DDIM * 3) {
        const float* tmp = x; x = w; w = tmp;
    }
    float* out = (float*)d_out;

    {   // split conversions
        size_t tx = (size_t)MROWS * IDIM;
        convx_kernel<<<(unsigned)((tx + 255) / 256), 256>>>(x);
        size_t tw = 3ull * IDIM * NCOLS;
        convw_kernel<<<(unsigned)((tw + 255) / 256), 256>>>(w);
    }
    {   // unified GEMM: v (8 blocks) + kq scores (16 heads)
        cudaFuncSetAttribute(gemm_kernel, cudaFuncAttributeMaxDynamicSharedMemorySize, SMEM_GEMM);
        dim3 grid(24, MROWS / BM);
        gemm_kernel<<<grid, 128, SMEM_GEMM>>>();
    }
    {   // chunked scan
        dim3 ga(BATCH, NCH - 1);
        scanA_kernel<<<ga, 512>>>();
        dim3 gb(BATCH, NCH);
        scanB_kernel<<<gb, 512>>>(out);
    }
}